// round 16
// baseline (speedup 1.0000x reference)
#include <cuda_runtime.h>
#include <cuda_bf16.h>
#include <cstdint>

// SimCLR supervised-contrastive loss, class-blocked, bf16 mma.sync GEMM.
// (tcgen05 unavailable: harness emits PTX .target sm_103 without 'a'.)
// R16: occupancy play. GEMM CTA tile 128x64, warp tile 32x32, acc=32 regs,
// launch_bounds(256,3) -> 24 warps/SM (was 16). Uniform upper-triangle
// coverage (cg > rg mask), every tile adds row+col sums; pos term harvested
// via packed perm XOR. Fused last-block final reduction.

#define NB 8192
#define BHALF 4096
#define D 512
#define NC 7
#define CHUNK 128
#define NCHUNK (NB/CHUNK)           // 64
#define TM 128                      // CTA tile rows
#define TN 64                       // CTA tile cols
#define NTI (NB/TM)                 // 64 row tiles
#define NTJ (NB/TN)                 // 128 col tiles
#define MAXTILES 4608
#define INV_T 2.0f
#define GEMM_GRID 444

// ---- scratch (__device__ globals; no allocation) ----
__device__ __nv_bfloat16 g_Gh[NB * D];   // class-sorted rows, bf16 (8 MB)
__device__ int   g_pl[NB];               // perm | (label<<16), sorted order
__device__ int   g_chunkcnt[NCHUNK * NC];
__device__ int   g_chunkbase[NCHUNK * NC];
__device__ float g_denom[NB];
__device__ float g_pos;
__device__ int   g_ntiles;
__device__ int   g_tiles[MAXTILES];
__device__ int   g_done;

// ---------------------------------------------------------------------------
__global__ __launch_bounds__(128) void k_hist(const int* __restrict__ labels) {
    __shared__ int s[NC];
    const int b = blockIdx.x, t = threadIdx.x;
    if (t < NC) s[t] = 0;
    __syncthreads();
    atomicAdd(&s[labels[b * CHUNK + t]], 1);
    g_denom[b * CHUNK + t] = 0.0f;
    __syncthreads();
    if (t < NC) g_chunkcnt[b * NC + t] = s[t];
}

// ---------------------------------------------------------------------------
// k_scan: scan 64x7 counters, class boundaries, g_pl labels, tile list.
__global__ __launch_bounds__(1024) void k_scan() {
    __shared__ int sex[NCHUNK][NC];
    __shared__ int sctot[NC];
    __shared__ int sbase[NC + 1];
    __shared__ int scnt;
    const int t = threadIdx.x, lane = t & 31, wid = t >> 5;

    if (wid < NC) {
        int v0 = g_chunkcnt[lane * NC + wid];
        int v1 = g_chunkcnt[(lane + 32) * NC + wid];
        int o0 = v0, o1 = v1;
#pragma unroll
        for (int off = 1; off < 32; off <<= 1) {
            int u = __shfl_up_sync(0xffffffffu, v0, off);
            if (lane >= off) v0 += u;
            u = __shfl_up_sync(0xffffffffu, v1, off);
            if (lane >= off) v1 += u;
        }
        int tot0 = __shfl_sync(0xffffffffu, v0, 31);
        sex[lane][wid] = v0 - o0;
        sex[lane + 32][wid] = tot0 + v1 - o1;
        if (lane == 31) sctot[wid] = tot0 + v1;
    }
    if (t == 0) { scnt = 0; g_done = 0; g_pos = 0.0f; }
    __syncthreads();
    if (t == 0) {
        int run = 0;
#pragma unroll
        for (int c = 0; c < NC; c++) { sbase[c] = run; run += sctot[c]; }
        sbase[NC] = run;
    }
    __syncthreads();
    if (t < NCHUNK * NC)
        g_chunkbase[t] = sbase[t % NC] + sex[t / NC][t % NC];

    auto classof = [&](int x) {
        int c = 0;
#pragma unroll
        for (int k = 1; k < NC; k++) c += (x >= sbase[k]);
        return c;
    };
    // seed labels into g_pl (perm filled later by k_scatgat; labels now)
    for (int p = t; p < NB; p += 1024)
        g_pl[p] = classof(p) << 16;   // low bits set by scatgat via add

    // tile list: i over 128-row tiles, j over 64-col tiles, keep j >= 2i
    for (int idx = t; idx < NTI * NTJ; idx += 1024) {
        int i = idx >> 7, j = idx & 127;
        if (j < 2 * i) continue;
        int rlo = classof(i * TM), rhi = classof(i * TM + TM - 1);
        int clo = classof(j * TN), chi = classof(j * TN + TN - 1);
        if (!(rhi < clo || chi < rlo)) {
            int p = atomicAdd(&scnt, 1);
            g_tiles[p] = (i << 16) | j;
        }
    }
    __syncthreads();
    if (t == 0) g_ntiles = scnt;
}

// ---------------------------------------------------------------------------
// k_scatgat: per-chunk stable ranks; writes perm (low bits of g_pl) and
// streams rows fp32->bf16 directly to class-sorted positions.
__global__ __launch_bounds__(256) void k_scatgat(const int* __restrict__ labels,
                                                 const float* __restrict__ outm) {
    __shared__ int slab[CHUNK];
    __shared__ int sdst[CHUNK];
    const int chunk = blockIdx.x >> 2, quarter = blockIdx.x & 3;
    const int tid = threadIdx.x;

    if (tid < CHUNK) slab[tid] = labels[chunk * CHUNK + tid];
    __syncthreads();
    if (tid < CHUNK) {
        int c = slab[tid], rank = 0;
        for (int s = 0; s < tid; s++) rank += (slab[s] == c);
        int dst = g_chunkbase[chunk * NC + c] + rank;
        sdst[tid] = dst;
        if (quarter == 0) atomicAdd(&g_pl[dst], chunk * CHUNK + tid);
    }
    __syncthreads();

    uint4* dstG = reinterpret_cast<uint4*>(g_Gh);
#pragma unroll
    for (int k = 0; k < 8; k++) {
        int idx = k * 256 + tid;
        int rl = quarter * 32 + (idx >> 6);
        int q = idx & 63;
        const float4* s =
            reinterpret_cast<const float4*>(outm + (size_t)(chunk * CHUNK + rl) * D) + q * 2;
        float4 a = s[0], b = s[1];
        __nv_bfloat162 h0 = __floats2bfloat162_rn(a.x, a.y);
        __nv_bfloat162 h1 = __floats2bfloat162_rn(a.z, a.w);
        __nv_bfloat162 h2 = __floats2bfloat162_rn(b.x, b.y);
        __nv_bfloat162 h3 = __floats2bfloat162_rn(b.z, b.w);
        uint4 o;
        o.x = *reinterpret_cast<uint32_t*>(&h0);
        o.y = *reinterpret_cast<uint32_t*>(&h1);
        o.z = *reinterpret_cast<uint32_t*>(&h2);
        o.w = *reinterpret_cast<uint32_t*>(&h3);
        dstG[(size_t)sdst[rl] * 64 + q] = o;
    }
}

// ---------------------------------------------------------------------------
// mma.sync helpers
__device__ __forceinline__ uint32_t smem_u32(const void* p) {
    uint32_t a;
    asm("{ .reg .u64 t; cvta.to.shared.u64 t, %1; cvt.u32.u64 %0, t; }" : "=r"(a) : "l"(p));
    return a;
}
__device__ __forceinline__ void ldsm_x4(uint32_t* r, uint32_t addr) {
    asm volatile("ldmatrix.sync.aligned.m8n8.x4.shared.b16 {%0,%1,%2,%3}, [%4];"
                 : "=r"(r[0]), "=r"(r[1]), "=r"(r[2]), "=r"(r[3]) : "r"(addr));
}
__device__ __forceinline__ void mma16816(float* d, const uint32_t* a,
                                         uint32_t b0, uint32_t b1) {
    asm volatile(
        "mma.sync.aligned.m16n8k16.row.col.f32.bf16.bf16.f32 "
        "{%0,%1,%2,%3}, {%4,%5,%6,%7}, {%8,%9}, {%0,%1,%2,%3};"
        : "+f"(d[0]), "+f"(d[1]), "+f"(d[2]), "+f"(d[3])
        : "r"(a[0]), "r"(a[1]), "r"(a[2]), "r"(a[3]), "r"(b0), "r"(b1));
}
__device__ __forceinline__ uint32_t sw64(int row, int c16) {
    return (uint32_t)(row * 128 + ((c16 ^ (row & 7)) << 4));
}

#define NKT (D / 64)          // 8
#define A_BYTES 16384         // 128 rows x 128B
#define B_BYTES 8192          // 64 rows x 128B
#define STAGE_BYTES (A_BYTES + B_BYTES)   // 24576
#define NSTAGE 3

__global__ void __launch_bounds__(256, 3) k_gemm_mma(float* __restrict__ outp) {
    extern __shared__ char dsm[];
    __shared__ float sdenR[TM];
    __shared__ float sdenC[TN];
    __shared__ int   spl[TM];    // perm | label<<16, rows
    __shared__ int   spc[TN];    // perm | label<<16, cols
    __shared__ float spos;
    __shared__ int   sdone;

    const int tid = threadIdx.x;
    const int wid = tid >> 5, lane = tid & 31;
    const int wm = wid >> 1, wn = wid & 1;        // 4x2 warps of 32x32
    const uint4* src = reinterpret_cast<const uint4*>(g_Gh);
    const uint32_t dyn = smem_u32(dsm);

    const int g = lane >> 3, r8 = lane & 7;
    const int row_off = ((g & 1) << 3) + r8;
    const int cch = g >> 1;
    const int qr = lane >> 2, qc = lane & 3;
    const int ntiles = g_ntiles;

    for (int w = blockIdx.x; w < ntiles; w += GEMM_GRID) {
        const int item = g_tiles[w];
        const int r0 = (item >> 16) * TM;
        const int c0 = (item & 0xffff) * TN;

        if (tid < TM) {
            spl[tid] = g_pl[r0 + tid];
            sdenR[tid] = 0.0f;
        }
        if (tid < TN) {
            spc[tid] = g_pl[c0 + tid];
            sdenC[tid] = 0.0f;
        }
        if (tid == 0) spos = 0.0f;

        auto issue = [&](int t, int st) {
            const uint32_t sa = dyn + st * STAGE_BYTES;
#pragma unroll
            for (int j = 0; j < 4; j++) {          // A: 128 rows
                int p = j * 256 + tid;
                int row = p >> 3, c16 = p & 7;
                const uint4* gA = src + (size_t)(r0 + row) * 64 + t * 8 + c16;
                uint32_t dA = sa + sw64(row, c16);
                asm volatile("cp.async.cg.shared.global [%0], [%1], 16;"
                             :: "r"(dA), "l"(gA));
            }
#pragma unroll
            for (int j = 0; j < 2; j++) {          // B: 64 rows
                int p = j * 256 + tid;
                int row = p >> 3, c16 = p & 7;
                const uint4* gB = src + (size_t)(c0 + row) * 64 + t * 8 + c16;
                uint32_t dB = sa + A_BYTES + sw64(row, c16);
                asm volatile("cp.async.cg.shared.global [%0], [%1], 16;"
                             :: "r"(dB), "l"(gB));
            }
            asm volatile("cp.async.commit_group;" ::: "memory");
        };

        issue(0, 0);
        issue(1, 1);

        float acc[2][4][4];
#pragma unroll
        for (int mf = 0; mf < 2; mf++)
#pragma unroll
            for (int nf = 0; nf < 4; nf++)
#pragma unroll
                for (int e = 0; e < 4; e++) acc[mf][nf][e] = 0.0f;

#pragma unroll
        for (int t = 0; t < NKT; t++) {
            if (t < NKT - 1) asm volatile("cp.async.wait_group 1;" ::: "memory");
            else             asm volatile("cp.async.wait_group 0;" ::: "memory");
            __syncthreads();
            if (t + 2 < NKT) issue(t + 2, (t + 2) % NSTAGE);

            const uint32_t sA = dyn + (t % NSTAGE) * STAGE_BYTES;
            const uint32_t sB = sA + A_BYTES;
#pragma unroll
            for (int kc = 0; kc < 4; kc++) {
                uint32_t amat[2][4], bmat[2][4];
                const int c16 = kc * 2 + cch;
#pragma unroll
                for (int mf = 0; mf < 2; mf++)
                    ldsm_x4(amat[mf], sA + sw64(wm * 32 + mf * 16 + row_off, c16));
#pragma unroll
                for (int nb = 0; nb < 2; nb++)
                    ldsm_x4(bmat[nb], sB + sw64(wn * 32 + nb * 16 + row_off, c16));
#pragma unroll
                for (int mf = 0; mf < 2; mf++)
#pragma unroll
                    for (int nf = 0; nf < 4; nf++)
                        mma16816(acc[mf][nf], amat[mf],
                                 bmat[nf >> 1][nf & 1], bmat[nf >> 1][2 + (nf & 1)]);
            }
        }

        // ---- epilogue: upper-triangle mask (cg > rg), same-class, exp;
        //      row sums AND col sums every tile; pos via packed XOR ----
        float colsum[4][2];
        float pos_acc = 0.0f;
#pragma unroll
        for (int nf = 0; nf < 4; nf++) { colsum[nf][0] = 0.0f; colsum[nf][1] = 0.0f; }

#pragma unroll
        for (int mf = 0; mf < 2; mf++) {
#pragma unroll
            for (int h = 0; h < 2; h++) {
                const int r = wm * 32 + mf * 16 + h * 8 + qr;
                const int rg = r0 + r;
                const int rpl = spl[r];
                float rs = 0.0f;
#pragma unroll
                for (int nf = 0; nf < 4; nf++) {
#pragma unroll
                    for (int e = 0; e < 2; e++) {
                        const int c = wn * 32 + nf * 8 + qc * 2 + e;
                        const int cg = c0 + c;
                        const float v = acc[mf][nf][h * 2 + e];
                        const int cpl = spc[c];
                        bool ok = ((rpl >> 16) == (cpl >> 16)) && (cg > rg);
                        float ex = ok ? __expf(INV_T * v) : 0.0f;
                        rs += ex;
                        colsum[nf][e] += ex;
                        // pos pair {i, i+B}: labels equal so full-int XOR
                        // == BHALF exactly for the positive pair
                        if (((rpl ^ cpl) == BHALF) && (cg > rg))
                            pos_acc += v;
                    }
                }
                rs += __shfl_xor_sync(0xffffffffu, rs, 1);
                rs += __shfl_xor_sync(0xffffffffu, rs, 2);
                if (qc == 0) atomicAdd(&sdenR[r], rs);
            }
        }
#pragma unroll
        for (int nf = 0; nf < 4; nf++) {
#pragma unroll
            for (int e = 0; e < 2; e++) {
                float cs = colsum[nf][e];
                cs += __shfl_xor_sync(0xffffffffu, cs, 4);
                cs += __shfl_xor_sync(0xffffffffu, cs, 8);
                cs += __shfl_xor_sync(0xffffffffu, cs, 16);
                if (qr == 0) {
                    const int c = wn * 32 + nf * 8 + qc * 2 + e;
                    atomicAdd(&sdenC[c], cs);
                }
            }
        }
        if (pos_acc != 0.0f) atomicAdd(&spos, pos_acc);
        __syncthreads();
        if (tid < TM) atomicAdd(&g_denom[r0 + tid], sdenR[tid]);
        if (tid < TN) atomicAdd(&g_denom[c0 + tid], sdenC[tid]);
        if (tid == 0 && spos != 0.0f) atomicAdd(&g_pos, spos);
        __syncthreads();
    }

    // ---- last-block final reduction ----
    __threadfence();
    __syncthreads();
    if (tid == 0) sdone = atomicAdd(&g_done, 1);
    __syncthreads();
    if (sdone == GEMM_GRID - 1) {
        __threadfence();
        __shared__ float red[8];
        float s = 0.0f;
#pragma unroll
        for (int j = 0; j < NB / 256; j++)
            s += __logf(g_denom[j * 256 + tid]);
#pragma unroll
        for (int off = 16; off > 0; off >>= 1)
            s += __shfl_xor_sync(0xffffffffu, s, off);
        if (lane == 0) red[wid] = s;
        __syncthreads();
        if (wid == 0) {
            float v = (lane < 8) ? red[lane] : 0.0f;
#pragma unroll
            for (int off = 4; off > 0; off >>= 1)
                v += __shfl_xor_sync(0xffffffffu, v, off);
            if (lane == 0)
                outp[0] = v / (float)NB - g_pos * (2.0f * INV_T) / (float)NB;
        }
    }
}

extern "C" void kernel_launch(void* const* d_in, const int* in_sizes, int n_in,
                              void* d_out, int out_size) {
    const float* out_m  = (const float*)d_in[0];   // [2B, D]
    const int*   labels = (const int*)d_in[3];     // [2B]
    float* loss = (float*)d_out;

    cudaFuncSetAttribute(k_gemm_mma, cudaFuncAttributeMaxDynamicSharedMemorySize,
                         NSTAGE * STAGE_BYTES);

    k_hist<<<NCHUNK, CHUNK>>>(labels);
    k_scan<<<1, 1024>>>();
    k_scatgat<<<256, 256>>>(labels, out_m);
    k_gemm_mma<<<GEMM_GRID, 256, NSTAGE * STAGE_BYTES>>>(loss);
}

// round 17
// speedup vs baseline: 1.0909x; 1.0909x over previous
#include <cuda_runtime.h>
#include <cuda_bf16.h>
#include <cstdint>

// SimCLR supervised-contrastive loss, class-blocked, bf16 mma.sync GEMM.
// (tcgen05 unavailable: harness emits PTX .target sm_103 without 'a'.)
// R17: MUFU was the hidden wall (exp for every tile entry). Fixes:
//  - rows pre-scaled by sqrt(2*log2e) so Gram output IS the ex2 argument
//  - epilogue uses ex2.approx.f16x2 (2 exps / MUFU op), f16x2 partial sums
//  - GEMM geometry reverted to the better R15 config (128x128, 64x32 warps)

#define NB 8192
#define BHALF 4096
#define D 512
#define NC 7
#define CHUNK 128
#define NCHUNK (NB/CHUNK)           // 64
#define TILE 128
#define NTILE (NB/TILE)             // 64
#define NPAIR (NTILE*(NTILE+1)/2)   // 2080
#define GEMM_GRID 296
// Gram prescale: y = (2*log2e)*dot ; exp(dot/T) = 2^y ; per-row sqrt factor
#define ROW_SCALE 1.698643600f
// loss pos coefficient: (2/T)/ (2*log2e) = 2*ln2
#define POS_COEF 1.386294361f

// ---- scratch (__device__ globals; no allocation) ----
__device__ __nv_bfloat16 g_Gh[NB * D];   // class-sorted scaled rows, bf16
__device__ int   g_pl[NB];               // perm | (label<<16), sorted order
__device__ int   g_chunkcnt[NCHUNK * NC];
__device__ int   g_chunkbase[NCHUNK * NC];
__device__ float g_denom[NB];
__device__ float g_pos;                  // sum of scaled pos-pair Gram values
__device__ int   g_ntiles;
__device__ int   g_tiles[NPAIR];
__device__ int   g_done;

// ---------------------------------------------------------------------------
__global__ __launch_bounds__(128) void k_hist(const int* __restrict__ labels) {
    __shared__ int s[NC];
    const int b = blockIdx.x, t = threadIdx.x;
    if (t < NC) s[t] = 0;
    __syncthreads();
    atomicAdd(&s[labels[b * CHUNK + t]], 1);
    g_denom[b * CHUNK + t] = 0.0f;
    __syncthreads();
    if (t < NC) g_chunkcnt[b * NC + t] = s[t];
}

// ---------------------------------------------------------------------------
__global__ __launch_bounds__(1024) void k_scan() {
    __shared__ int sex[NCHUNK][NC];
    __shared__ int sctot[NC];
    __shared__ int sbase[NC + 1];
    __shared__ int scnt;
    const int t = threadIdx.x, lane = t & 31, wid = t >> 5;

    if (wid < NC) {
        int v0 = g_chunkcnt[lane * NC + wid];
        int v1 = g_chunkcnt[(lane + 32) * NC + wid];
        int o0 = v0, o1 = v1;
#pragma unroll
        for (int off = 1; off < 32; off <<= 1) {
            int u = __shfl_up_sync(0xffffffffu, v0, off);
            if (lane >= off) v0 += u;
            u = __shfl_up_sync(0xffffffffu, v1, off);
            if (lane >= off) v1 += u;
        }
        int tot0 = __shfl_sync(0xffffffffu, v0, 31);
        sex[lane][wid] = v0 - o0;
        sex[lane + 32][wid] = tot0 + v1 - o1;
        if (lane == 31) sctot[wid] = tot0 + v1;
    }
    if (t == 0) { scnt = 0; g_done = 0; g_pos = 0.0f; }
    __syncthreads();
    if (t == 0) {
        int run = 0;
#pragma unroll
        for (int c = 0; c < NC; c++) { sbase[c] = run; run += sctot[c]; }
        sbase[NC] = run;
    }
    __syncthreads();
    if (t < NCHUNK * NC)
        g_chunkbase[t] = sbase[t % NC] + sex[t / NC][t % NC];

    auto classof = [&](int x) {
        int c = 0;
#pragma unroll
        for (int k = 1; k < NC; k++) c += (x >= sbase[k]);
        return c;
    };
    for (int p = t; p < NB; p += 1024)
        g_pl[p] = classof(p) << 16;   // perm low bits added by k_scatgat

    // tile list: upper-triangular (j >= i) 128x128 tiles with class overlap
    for (int idx = t; idx < NTILE * NTILE; idx += 1024) {
        int i = idx >> 6, j = idx & 63;
        if (j < i) continue;
        int rlo = classof(i * TILE), rhi = classof(i * TILE + TILE - 1);
        int clo = classof(j * TILE), chi = classof(j * TILE + TILE - 1);
        if (!(rhi < clo || chi < rlo)) {
            int p = atomicAdd(&scnt, 1);
            g_tiles[p] = (i << 16) | j;
        }
    }
    __syncthreads();
    if (t == 0) g_ntiles = scnt;
}

// ---------------------------------------------------------------------------
// k_scatgat: per-chunk stable ranks; writes perm; streams rows fp32 -> bf16
// (pre-scaled by ROW_SCALE) directly to class-sorted positions.
__global__ __launch_bounds__(256) void k_scatgat(const int* __restrict__ labels,
                                                 const float* __restrict__ outm) {
    __shared__ int slab[CHUNK];
    __shared__ int sdst[CHUNK];
    const int chunk = blockIdx.x >> 2, quarter = blockIdx.x & 3;
    const int tid = threadIdx.x;

    if (tid < CHUNK) slab[tid] = labels[chunk * CHUNK + tid];
    __syncthreads();
    if (tid < CHUNK) {
        int c = slab[tid], rank = 0;
        for (int s = 0; s < tid; s++) rank += (slab[s] == c);
        int dst = g_chunkbase[chunk * NC + c] + rank;
        sdst[tid] = dst;
        if (quarter == 0) atomicAdd(&g_pl[dst], chunk * CHUNK + tid);
    }
    __syncthreads();

    uint4* dstG = reinterpret_cast<uint4*>(g_Gh);
#pragma unroll
    for (int k = 0; k < 8; k++) {
        int idx = k * 256 + tid;
        int rl = quarter * 32 + (idx >> 6);
        int q = idx & 63;
        const float4* s =
            reinterpret_cast<const float4*>(outm + (size_t)(chunk * CHUNK + rl) * D) + q * 2;
        float4 a = s[0], b = s[1];
        __nv_bfloat162 h0 = __floats2bfloat162_rn(a.x * ROW_SCALE, a.y * ROW_SCALE);
        __nv_bfloat162 h1 = __floats2bfloat162_rn(a.z * ROW_SCALE, a.w * ROW_SCALE);
        __nv_bfloat162 h2 = __floats2bfloat162_rn(b.x * ROW_SCALE, b.y * ROW_SCALE);
        __nv_bfloat162 h3 = __floats2bfloat162_rn(b.z * ROW_SCALE, b.w * ROW_SCALE);
        uint4 o;
        o.x = *reinterpret_cast<uint32_t*>(&h0);
        o.y = *reinterpret_cast<uint32_t*>(&h1);
        o.z = *reinterpret_cast<uint32_t*>(&h2);
        o.w = *reinterpret_cast<uint32_t*>(&h3);
        dstG[(size_t)sdst[rl] * 64 + q] = o;
    }
}

// ---------------------------------------------------------------------------
// mma.sync helpers
__device__ __forceinline__ uint32_t smem_u32(const void* p) {
    uint32_t a;
    asm("{ .reg .u64 t; cvta.to.shared.u64 t, %1; cvt.u32.u64 %0, t; }" : "=r"(a) : "l"(p));
    return a;
}
__device__ __forceinline__ void ldsm_x4(uint32_t* r, uint32_t addr) {
    asm volatile("ldmatrix.sync.aligned.m8n8.x4.shared.b16 {%0,%1,%2,%3}, [%4];"
                 : "=r"(r[0]), "=r"(r[1]), "=r"(r[2]), "=r"(r[3]) : "r"(addr));
}
__device__ __forceinline__ void mma16816(float* d, const uint32_t* a,
                                         uint32_t b0, uint32_t b1) {
    asm volatile(
        "mma.sync.aligned.m16n8k16.row.col.f32.bf16.bf16.f32 "
        "{%0,%1,%2,%3}, {%4,%5,%6,%7}, {%8,%9}, {%0,%1,%2,%3};"
        : "+f"(d[0]), "+f"(d[1]), "+f"(d[2]), "+f"(d[3])
        : "r"(a[0]), "r"(a[1]), "r"(a[2]), "r"(a[3]), "r"(b0), "r"(b1));
}
__device__ __forceinline__ uint32_t sw64(int row, int c16) {
    return (uint32_t)(row * 128 + ((c16 ^ (row & 7)) << 4));
}
// pack two f32 -> f16x2 ({hi=v1, lo=v0}), ex2, hadd2
__device__ __forceinline__ uint32_t pack_h2(float v1, float v0) {
    uint32_t d;
    asm("cvt.rn.f16x2.f32 %0, %1, %2;" : "=r"(d) : "f"(v1), "f"(v0));
    return d;
}
__device__ __forceinline__ uint32_t ex2_h2(uint32_t a) {
    uint32_t d;
    asm("ex2.approx.f16x2 %0, %1;" : "=r"(d) : "r"(a));
    return d;
}
__device__ __forceinline__ uint32_t hadd2(uint32_t a, uint32_t b) {
    uint32_t d;
    asm("add.rn.f16x2 %0, %1, %2;" : "=r"(d) : "r"(a), "r"(b));
    return d;
}
__device__ __forceinline__ float2 h2_to_f2(uint32_t a) {
    __half2 h = *reinterpret_cast<__half2*>(&a);
    return __half22float2(h);   // .x = lo, .y = hi
}

#define NKT (D / 64)          // 8
#define STAGE_BYTES 32768     // A 16KB + B 16KB
#define NSTAGE 3

__global__ void __launch_bounds__(256, 2) k_gemm_mma(float* __restrict__ outp) {
    extern __shared__ char dsm[];
    __shared__ float sdenR[TILE];
    __shared__ float sdenC[TILE];
    __shared__ int   spl[TILE], spc[TILE];   // perm | label<<16
    __shared__ float spos;
    __shared__ int   sdone;

    const int tid = threadIdx.x;
    const int wid = tid >> 5, lane = tid & 31;
    const int wm = wid >> 2, wn = wid & 3;        // warp tile 64x32
    const uint4* src = reinterpret_cast<const uint4*>(g_Gh);
    const uint32_t dyn = smem_u32(dsm);

    const int g = lane >> 3, r8 = lane & 7;
    const int row_off = ((g & 1) << 3) + r8;
    const int cch = g >> 1;
    const int qr = lane >> 2, qc = lane & 3;
    const int ntiles = g_ntiles;

    for (int w = blockIdx.x; w < ntiles; w += GEMM_GRID) {
        const int item = g_tiles[w];
        const int r0 = (item >> 16) * TILE;
        const int c0 = (item & 0xffff) * TILE;
        const bool offdiag = (c0 != r0);

        if (tid < TILE) {
            spl[tid] = g_pl[r0 + tid];
            spc[tid] = g_pl[c0 + tid];
            sdenR[tid] = 0.0f;
            sdenC[tid] = 0.0f;
        }
        if (tid == 0) spos = 0.0f;

        auto issue = [&](int t, int st) {
            const uint32_t sa = dyn + st * STAGE_BYTES;
#pragma unroll
            for (int j = 0; j < 4; j++) {
                int p = j * 256 + tid;
                int row = p >> 3, c16 = p & 7;
                const uint4* gA = src + (size_t)(r0 + row) * 64 + t * 8 + c16;
                const uint4* gB = src + (size_t)(c0 + row) * 64 + t * 8 + c16;
                uint32_t dA = sa + sw64(row, c16);
                uint32_t dB = sa + 16384 + sw64(row, c16);
                asm volatile("cp.async.cg.shared.global [%0], [%1], 16;\n\t"
                             "cp.async.cg.shared.global [%2], [%3], 16;"
                             :: "r"(dA), "l"(gA), "r"(dB), "l"(gB));
            }
            asm volatile("cp.async.commit_group;" ::: "memory");
        };

        issue(0, 0);
        issue(1, 1);

        float acc[4][4][4];
#pragma unroll
        for (int mf = 0; mf < 4; mf++)
#pragma unroll
            for (int nf = 0; nf < 4; nf++)
#pragma unroll
                for (int e = 0; e < 4; e++) acc[mf][nf][e] = 0.0f;

#pragma unroll
        for (int t = 0; t < NKT; t++) {
            if (t < NKT - 1) asm volatile("cp.async.wait_group 1;" ::: "memory");
            else             asm volatile("cp.async.wait_group 0;" ::: "memory");
            __syncthreads();
            if (t + 2 < NKT) issue(t + 2, (t + 2) % NSTAGE);

            const uint32_t sA = dyn + (t % NSTAGE) * STAGE_BYTES;
            const uint32_t sB = sA + 16384;
#pragma unroll
            for (int kc = 0; kc < 4; kc++) {
                uint32_t amat[4][4], bmat[2][4];
                const int c16 = kc * 2 + cch;
#pragma unroll
                for (int mf = 0; mf < 4; mf++)
                    ldsm_x4(amat[mf], sA + sw64(wm * 64 + mf * 16 + row_off, c16));
#pragma unroll
                for (int nb = 0; nb < 2; nb++)
                    ldsm_x4(bmat[nb], sB + sw64(wn * 32 + nb * 16 + row_off, c16));
#pragma unroll
                for (int mf = 0; mf < 4; mf++)
#pragma unroll
                    for (int nf = 0; nf < 4; nf++)
                        mma16816(acc[mf][nf], amat[mf],
                                 bmat[nf >> 1][nf & 1], bmat[nf >> 1][2 + (nf & 1)]);
            }
        }

        // ---- epilogue: mask + ex2.f16x2; row sums always, col sums if
        //      offdiag; pos harvest via packed XOR == BHALF ----
        uint32_t cs2[4];
#pragma unroll
        for (int nf = 0; nf < 4; nf++) cs2[nf] = 0u;
        float pos_acc = 0.0f;

#pragma unroll
        for (int mf = 0; mf < 4; mf++) {
#pragma unroll
            for (int h = 0; h < 2; h++) {
                const int r = wm * 64 + mf * 16 + h * 8 + qr;
                const int rg = r0 + r;
                const int rpl = spl[r];
                uint32_t rs2 = 0u;
#pragma unroll
                for (int nf = 0; nf < 4; nf++) {
                    const int ci0 = wn * 32 + nf * 8 + qc * 2;
                    const int cpl0 = spc[ci0], cpl1 = spc[ci0 + 1];
                    const float v0 = acc[mf][nf][h * 2 + 0];
                    const float v1 = acc[mf][nf][h * 2 + 1];
                    const bool ok0 = (((rpl ^ cpl0) >> 16) == 0) && (rg != c0 + ci0);
                    const bool ok1 = (((rpl ^ cpl1) >> 16) == 0) && (rg != c0 + ci0 + 1);
                    const float x0 = ok0 ? v0 : -100.0f;
                    const float x1 = ok1 ? v1 : -100.0f;
                    const uint32_t ex = ex2_h2(pack_h2(x1, x0));
                    rs2 = hadd2(rs2, ex);
                    cs2[nf] = hadd2(cs2[nf], ex);
                    if (((rpl ^ cpl0) == BHALF) && (offdiag || r < ci0))
                        pos_acc += v0;
                    if (((rpl ^ cpl1) == BHALF) && (offdiag || r < ci0 + 1))
                        pos_acc += v1;
                }
                float2 fr = h2_to_f2(rs2);
                float rs = fr.x + fr.y;
                rs += __shfl_xor_sync(0xffffffffu, rs, 1);
                rs += __shfl_xor_sync(0xffffffffu, rs, 2);
                if (qc == 0) atomicAdd(&sdenR[r], rs);
            }
        }
        if (offdiag) {
#pragma unroll
            for (int nf = 0; nf < 4; nf++) {
                float2 fc = h2_to_f2(cs2[nf]);
#pragma unroll
                for (int e = 0; e < 2; e++) {
                    float cs = (e == 0) ? fc.x : fc.y;
                    cs += __shfl_xor_sync(0xffffffffu, cs, 4);
                    cs += __shfl_xor_sync(0xffffffffu, cs, 8);
                    cs += __shfl_xor_sync(0xffffffffu, cs, 16);
                    if (qr == 0) {
                        const int c = wn * 32 + nf * 8 + qc * 2 + e;
                        atomicAdd(&sdenC[c], cs);
                    }
                }
            }
        }
        if (pos_acc != 0.0f) atomicAdd(&spos, pos_acc);
        __syncthreads();
        if (tid < TILE) {
            atomicAdd(&g_denom[r0 + tid], sdenR[tid]);
            if (offdiag) atomicAdd(&g_denom[c0 + tid], sdenC[tid]);
        }
        if (tid == 0 && spos != 0.0f) atomicAdd(&g_pos, spos);
        __syncthreads();
    }

    // ---- last-block final reduction ----
    __threadfence();
    __syncthreads();
    if (tid == 0) sdone = atomicAdd(&g_done, 1);
    __syncthreads();
    if (sdone == GEMM_GRID - 1) {
        __threadfence();
        __shared__ float red[8];
        float s = 0.0f;
#pragma unroll
        for (int j = 0; j < NB / 256; j++)
            s += __logf(g_denom[j * 256 + tid]);
#pragma unroll
        for (int off = 16; off > 0; off >>= 1)
            s += __shfl_xor_sync(0xffffffffu, s, off);
        if (lane == 0) red[wid] = s;
        __syncthreads();
        if (wid == 0) {
            float v = (lane < 8) ? red[lane] : 0.0f;
#pragma unroll
            for (int off = 4; off > 0; off >>= 1)
                v += __shfl_xor_sync(0xffffffffu, v, off);
            if (lane == 0)
                outp[0] = v / (float)NB - g_pos * POS_COEF / (float)NB;
        }
    }
}

extern "C" void kernel_launch(void* const* d_in, const int* in_sizes, int n_in,
                              void* d_out, int out_size) {
    const float* out_m  = (const float*)d_in[0];   // [2B, D]
    const int*   labels = (const int*)d_in[3];     // [2B]
    float* loss = (float*)d_out;

    cudaFuncSetAttribute(k_gemm_mma, cudaFuncAttributeMaxDynamicSharedMemorySize,
                         NSTAGE * STAGE_BYTES);

    k_hist<<<NCHUNK, CHUNK>>>(labels);
    k_scan<<<1, 1024>>>();
    k_scatgat<<<256, 256>>>(labels, out_m);
    k_gemm_mma<<<GEMM_GRID, 256, NSTAGE * STAGE_BYTES>>>(loss);
}